// round 10
// baseline (speedup 1.0000x reference)
#include <cuda_runtime.h>

// Shapes (this instance): B=2048, L=196, M=16, NBL=10. Derived from in_sizes.
#define MAXSITES 256
#define TILE_B  2048                  // 128 float4, unpadded (broadcast reads)
#define NSLOT   4
#define RING_B  (NSLOT * 4 * TILE_B)  // 4 slots x (2 dirs x 2 sites) = 32768 B
#define SLR_B   1024                  // 2 dirs x 8 samples x 16 floats

typedef unsigned long long ull;

// Column-form paired tensors (R3-validated layout):
//  mat4L[s][m*8+q] = {A0[m][q], A0[m][q+8], A1[m][q], A1[m][q+8]}
//  mat4R[s'][n*8+q] = {A0[q][n], A0[q+8][n], A1[q][n], A1[q+8][n]}, s' reversed
__device__ float4 g_mat4L[MAXSITES * 128];
__device__ float4 g_mat4R[MAXSITES * 128];
__device__ unsigned g_count = 0;
__device__ volatile unsigned g_gen = 0;

// ---------------------------------------------------------------------------
__device__ __forceinline__ ull pack2(float x, float y) {
    ull r; asm("mov.b64 %0, {%1,%2};" : "=l"(r) : "f"(x), "f"(y)); return r;
}
__device__ __forceinline__ void unpack2(ull v, float& x, float& y) {
    asm("mov.b64 {%0,%1}, %2;" : "=f"(x), "=f"(y) : "l"(v));
}
__device__ __forceinline__ void fma2(ull& d, ull a, ull b) {
    asm("fma.rn.f32x2 %0, %1, %2, %0;" : "+l"(d) : "l"(a), "l"(b));
}
__device__ __forceinline__ ull mul2(ull a, ull b) {
    ull d; asm("mul.rn.f32x2 %0, %1, %2;" : "=l"(d) : "l"(a), "l"(b)); return d;
}
__device__ __forceinline__ ull add2(ull a, ull b) {
    ull d; asm("add.rn.f32x2 %0, %1, %2;" : "=l"(d) : "l"(a), "l"(b)); return d;
}
__device__ __forceinline__ void cpasync16(unsigned dst, const void* src) {
    asm volatile("cp.async.cg.shared.global [%0], [%1], 16;\n"
                 :: "r"(dst), "l"(src) : "memory");
}
__device__ __forceinline__ void cpcommit() {
    asm volatile("cp.async.commit_group;\n" ::: "memory");
}
template<int N> __device__ __forceinline__ void cpwait() {
    asm volatile("cp.async.wait_group %0;\n" :: "n"(N) : "memory");
}

// ---------------------------------------------------------------------------
// Megakernel: prep -> grid barrier -> chains (v in registers, shfl exchange)
// -> fused combine.  Block = 128 thr = 8 samples; 256 blocks (~2/SM).
// Warp layout: w0,w1 LEFT / w2,w3 RIGHT; lane: q = lane&7 (owns components
// q and q+8), group g = lane>>3 selects the sample. 4 chains per warp.
// ---------------------------------------------------------------------------
__global__ void __launch_bounds__(128, 2)
mega_kernel(const float* __restrict__ inputs,
            const float* __restrict__ A_left,
            const float* __restrict__ A_mid,
            const float* __restrict__ A_right,
            const float* __restrict__ T,
            const int*   __restrict__ pos_ptr,
            float* __restrict__ out,
            int B, int L, int NBL, int nblocks) {
    extern __shared__ __align__(16) char smem[];
    const int Lm2 = L - 2;
    float4* ring = (float4*)smem;                        // RING_B
    float*  sLR  = (float*)(smem + RING_B);              // SLR_B

    int tid  = threadIdx.x;
    int w    = tid >> 5;
    int lane = tid & 31;
    int q    = lane & 7;
    int g    = lane >> 3;                                // sample group 0..3

    const float2* in2 = (const float2*)inputs;           // (B,L) float2

    // ---- prep: pack A_mid into column-form mat4L / mat4R (reversed) --------
    for (int s = blockIdx.x; s < Lm2; s += nblocks) {
        int e = tid;                                     // 0..127 = m*8+qq
        int m = e >> 3, qq = e & 7;
        const float* A0 = A_mid + s * 512;
        const float* A1 = A0 + 256;
        float4 L4 = make_float4(A0[m * 16 + qq],       A0[m * 16 + qq + 8],
                                A1[m * 16 + qq],       A1[m * 16 + qq + 8]);
        float4 R4 = make_float4(A0[qq * 16 + m],       A0[(qq + 8) * 16 + m],
                                A1[qq * 16 + m],       A1[(qq + 8) * 16 + m]);
        g_mat4L[s * 128 + e] = L4;
        g_mat4R[(Lm2 - 1 - s) * 128 + e] = R4;
    }

    // ---- grid barrier (generation-based; 256 blocks co-resident) -----------
    __threadfence();
    __syncthreads();
    if (tid == 0) {
        unsigned gen = g_gen;
        if (atomicAdd(&g_count, 1) == (unsigned)(nblocks - 1)) {
            g_count = 0;
            __threadfence();
            g_gen = gen + 1;
        } else {
            while (g_gen == gen) __nanosleep(64);
        }
        __threadfence();
    }
    __syncthreads();

    // ---- chain setup --------------------------------------------------------
    int pos = __ldg(pos_ptr);
    bool isLeft = (w < 2);
    int sm = (w & 1) * 4 + g;              // local sample 0..7
    int c  = blockIdx.x * 8 + sm;          // global sample
    int nsL = pos, nsR = Lm2 - pos;
    int nsites = isLeft ? nsL : nsR;
    const float* seedA = isLeft ? A_left : A_right;
    int seedX = isLeft ? 0 : (L - 1);

    float2 xs = __ldg(in2 + c * L + seedX);
    float v0 = fmaf(xs.y, __ldg(seedA + 16 + q),     xs.x * __ldg(seedA + q));
    float v1 = fmaf(xs.y, __ldg(seedA + 16 + q + 8), xs.x * __ldg(seedA + q + 8));

    unsigned ringAddr = (unsigned)__cvta_generic_to_shared(ring);

    auto stage_pair = [&](int p, int slot) {
        int s0 = 2 * p;
#pragma unroll
        for (int kk = 0; kk < 4; ++kk) {
            int chunk  = tid + kk * 128;           // 0..511
            int tile   = chunk >> 7;               // 0,1: L sites | 2,3: R sites
            int within = chunk & 127;
            int site   = s0 + (tile & 1);
            bool isR   = (tile >> 1) != 0;
            if (site < (isR ? nsR : nsL)) {
                const float4* src = (isR ? g_mat4R : g_mat4L) + site * 128 + within;
                unsigned dst = ringAddr + slot * (4 * TILE_B) + tile * TILE_B
                             + within * 16;
                cpasync16(dst, src);
            }
        }
        cpcommit();
    };

    auto do_site = [&](int s, int slot) {
        if (s >= nsites) return;
        const char* tile = (const char*)ring + slot * (4 * TILE_B)
                         + (isLeft ? 0 : 2 * TILE_B) + (s & 1) * TILE_B;
        int xsite = isLeft ? (1 + s) : (L - 2 - s);
        float2 x = __ldg(in2 + c * L + xsite);

        // broadcast v components within the 8-lane group (no smem, no sync)
        float vmf[16];
#pragma unroll
        for (int m = 0; m < 8; ++m)
            vmf[m] = __shfl_sync(0xffffffffu, v0, m, 8);
#pragma unroll
        for (int m = 0; m < 8; ++m)
            vmf[8 + m] = __shfl_sync(0xffffffffu, v1, m, 8);

        ull a0e = 0ull, a0o = 0ull, a1e = 0ull, a1o = 0ull;
#pragma unroll
        for (int m = 0; m < 16; ++m) {
            ulonglong2 M = *(const ulonglong2*)(tile + (m * 8 + q) * 16);
            ull vmm = pack2(vmf[m], vmf[m]);
            if (m & 1) { fma2(a0o, vmm, M.x); fma2(a1o, vmm, M.y); }
            else       { fma2(a0e, vmm, M.x); fma2(a1e, vmm, M.y); }
        }
        ull xx0 = pack2(x.x, x.x);
        ull xx1 = pack2(x.y, x.y);
        ull tt = mul2(xx0, add2(a0e, a0o));
        fma2(tt, xx1, add2(a1e, a1o));
        unpack2(tt, v0, v1);
    };

    // ---- main loop: 2 sites per barrier, 4-slot ring, 2 pairs of slack ------
    int maxs = nsL > nsR ? nsL : nsR;
    int P = (maxs + 1) >> 1;
    if (P > 0) stage_pair(0, 0); else cpcommit();
    if (P > 1) stage_pair(1, 1); else cpcommit();
    if (P > 2) stage_pair(2, 2); else cpcommit();
    for (int t = 0; t < P; ++t) {
        cpwait<2>();            // pair t resident (t+1, t+2 may be in flight)
        __syncthreads();        // all warps past pair t-1; slot (t+3)%4 free
        if (t + 3 < P) stage_pair(t + 3, (t + 3) & 3); else cpcommit();
        do_site(2 * t,     t & 3);
        do_site(2 * t + 1, t & 3);
    }
    cpwait<0>();

    // ---- publish chain results, fused combine -------------------------------
    float* sL = sLR;
    float* sR = sLR + 128;
    {
        float* d = (isLeft ? sL : sR) + sm * 16;
        d[q] = v0; d[q + 8] = v1;
    }
    __syncthreads();

    float* sT = (float*)ring;                       // reuse ring for T
    int tElems = 256 * NBL;
    for (int i = tid; i < tElems; i += 128) sT[i] = __ldg(T + i);
    __syncthreads();

    int total = 8 * NBL;
    if (tid < total) {
        int b = tid / NBL, l = tid - b * NBL;
        float acc = 0.f;
#pragma unroll
        for (int m = 0; m < 16; ++m) {
            float t2 = 0.f;
#pragma unroll
            for (int k = 0; k < 16; ++k)
                t2 = fmaf(sT[(m * 16 + k) * NBL + l], sR[b * 16 + k], t2);
            acc = fmaf(sL[b * 16 + m], t2, acc);
        }
        out[(blockIdx.x * 8 + b) * NBL + l] = acc;
    }
}

// ---------------------------------------------------------------------------
extern "C" void kernel_launch(void* const* d_in, const int* in_sizes, int n_in,
                              void* d_out, int out_size) {
    const float* inputs  = (const float*)d_in[0];
    const float* A_left  = (const float*)d_in[1];
    const float* A_mid   = (const float*)d_in[2];
    const float* A_right = (const float*)d_in[3];
    const float* T_out   = (const float*)d_in[4];
    const int*   pos     = (const int*)d_in[5];

    int Lm2 = in_sizes[2] / 512;          // L-2 = 194
    int L   = Lm2 + 2;                    // 196
    int B   = in_sizes[0] / (2 * L);      // 2048
    int NBL = in_sizes[4] / 256;          // 10

    int nblocks = B / 8;                  // 256
    size_t smemB = (size_t)RING_B + SLR_B;   // ~33 KB

    cudaFuncSetAttribute(mega_kernel,
                         cudaFuncAttributeMaxDynamicSharedMemorySize,
                         (int)smemB);

    mega_kernel<<<nblocks, 128, smemB>>>(inputs, A_left, A_mid, A_right,
                                         T_out, pos, (float*)d_out,
                                         B, L, NBL, nblocks);
}

// round 11
// speedup vs baseline: 1.3800x; 1.3800x over previous
#include <cuda_runtime.h>

// Shapes (this instance): B=2048, L=196, M=16, NBL=10. Derived from in_sizes.
#define MAXSITES 256
#define MAXPAIRS 128
#define QTILE_B 4096                  // fused pair tile: 256 float4
#define SLOT_B  (2 * QTILE_B)         // L tile + R tile
#define NSLOT   4
#define RING_B  (NSLOT * SLOT_B)      // 32768 B
#define VSTRIDE 18                    // float2 per chain row (144B, conflict-free)
#define SV_B    (2 * 32 * VSTRIDE * 8)  // 9216 B (2 bufs x 32 chains)
#define SLR_B   2048

typedef unsigned long long ull;

// Fused pair tensors:
//  g_QL[p]: left pair p (sites 2p,2p+1):  tile half0[(m*8+q)] = {P00[m][q],P00[m][q+8],P01[m][q],P01[m][q+8]}
//           half1 = {P10...,P11...};  P_ij = A_i[2p] @ A_j[2p+1]
//  g_QR[p]: right pair p, transposed form; P_ij = A_i[Lm2-2-2p] @ A_j[Lm2-1-2p]
__device__ float4 g_QL[MAXPAIRS * 256];
__device__ float4 g_QR[MAXPAIRS * 256];
// Single-site column-form packs (tail steps when nsites is odd):
__device__ float4 g_mat4L[MAXSITES * 128];
__device__ float4 g_mat4R[MAXSITES * 128];
__device__ unsigned g_count = 0;
__device__ volatile unsigned g_gen = 0;

// ---------------------------------------------------------------------------
__device__ __forceinline__ ull pack2(float x, float y) {
    ull r; asm("mov.b64 %0, {%1,%2};" : "=l"(r) : "f"(x), "f"(y)); return r;
}
__device__ __forceinline__ void unpack2(ull v, float& x, float& y) {
    asm("mov.b64 {%0,%1}, %2;" : "=f"(x), "=f"(y) : "l"(v));
}
__device__ __forceinline__ void fma2(ull& d, ull a, ull b) {
    asm("fma.rn.f32x2 %0, %1, %2, %0;" : "+l"(d) : "l"(a), "l"(b));
}
__device__ __forceinline__ ull mul2(ull a, ull b) {
    ull d; asm("mul.rn.f32x2 %0, %1, %2;" : "=l"(d) : "l"(a), "l"(b)); return d;
}
__device__ __forceinline__ void cpasync16(unsigned dst, const void* src) {
    asm volatile("cp.async.cg.shared.global [%0], [%1], 16;\n"
                 :: "r"(dst), "l"(src) : "memory");
}
__device__ __forceinline__ void cpcommit() {
    asm volatile("cp.async.commit_group;\n" ::: "memory");
}
template<int N> __device__ __forceinline__ void cpwait() {
    asm volatile("cp.async.wait_group %0;\n" :: "n"(N) : "memory");
}

// ---------------------------------------------------------------------------
// Megakernel: prep (mat4 + fused pair products) -> grid barrier -> fused
// chains -> fused combine.  Block = 128 thr = 16 samples; 128 blocks (1/SM).
// Warps 0,1: LEFT; 2,3: RIGHT. Lane: q=lane&7 owns components {q,q+8} of two
// samples (2 chains/lane, 8 chains/warp). v exchanged via smem splats.
// ---------------------------------------------------------------------------
__global__ void __launch_bounds__(128, 1)
mega_kernel(const float* __restrict__ inputs,
            const float* __restrict__ A_left,
            const float* __restrict__ A_mid,
            const float* __restrict__ A_right,
            const float* __restrict__ T,
            const int*   __restrict__ pos_ptr,
            float* __restrict__ out,
            int B, int L, int NBL, int nblocks) {
    extern __shared__ __align__(16) char smem[];
    const int Lm2 = L - 2;
    char*   ring = smem;                                 // RING_B
    float2* sVs  = (float2*)(smem + RING_B);             // SV_B
    float*  sLR  = (float*)(smem + RING_B + SV_B);       // SLR_B

    int tid  = threadIdx.x;
    int w    = tid >> 5;
    int lane = tid & 31;
    int q    = lane & 7;
    int ch   = lane >> 3;                                // 0..3

    const float2* in2 = (const float2*)inputs;           // (B,L) float2

    // ---- prep A: single-site column packs (for odd tails) ------------------
    for (int s = blockIdx.x; s < Lm2; s += nblocks) {
        int m = tid >> 3, qq = tid & 7;
        const float* A0 = A_mid + s * 512;
        const float* A1 = A0 + 256;
        float4 L4 = make_float4(A0[m * 16 + qq],  A0[m * 16 + qq + 8],
                                A1[m * 16 + qq],  A1[m * 16 + qq + 8]);
        float4 R4 = make_float4(A0[qq * 16 + m],  A0[(qq + 8) * 16 + m],
                                A1[qq * 16 + m],  A1[(qq + 8) * 16 + m]);
        g_mat4L[s * 128 + tid] = L4;
        g_mat4R[(Lm2 - 1 - s) * 128 + tid] = R4;
    }

    // ---- prep B: fused pair products ---------------------------------------
    {
        float* sF = (float*)ring;            // site of factor i (512 floats)
        float* sS = sF + 512;                // site of factor j
        int PL = Lm2 >> 1;                   // full pairs per direction
        for (int job = blockIdx.x; job < 2 * PL; job += nblocks) {
            bool right = (job >= PL);
            int p = right ? job - PL : job;
            int sFirst  = right ? (Lm2 - 2 - 2 * p) : (2 * p);
            int sSecond = right ? (Lm2 - 1 - 2 * p) : (2 * p + 1);
            __syncthreads();
            ((float4*)sF)[tid] = __ldg((const float4*)(A_mid + sFirst  * 512) + tid);
            ((float4*)sS)[tid] = __ldg((const float4*)(A_mid + sSecond * 512) + tid);
            __syncthreads();
            int m = tid >> 3, qq = tid & 7;
            // left: out(m, n) = sum_k F_i[m][k] * S_j[k][n],       n = qq, qq+8
            // right (transposed store): out(m,n) = P[n][m] = sum_k F_i[n][k]*S_j[k][m]
            int rA0 = right ? qq       : m;
            int rA1 = right ? (qq + 8) : m;
            int cB0 = right ? m        : qq;
            int cB1 = right ? m        : (qq + 8);
            float v00a=0,v00b=0,v01a=0,v01b=0,v10a=0,v10b=0,v11a=0,v11b=0;
#pragma unroll
            for (int k = 0; k < 16; ++k) {
                float f0a = sF[rA0 * 16 + k],        f0b = sF[rA1 * 16 + k];
                float f1a = sF[256 + rA0 * 16 + k],  f1b = sF[256 + rA1 * 16 + k];
                float s0a = sS[k * 16 + cB0],        s0b = sS[k * 16 + cB1];
                float s1a = sS[256 + k * 16 + cB0],  s1b = sS[256 + k * 16 + cB1];
                v00a = fmaf(f0a, s0a, v00a);  v00b = fmaf(f0b, s0b, v00b);
                v01a = fmaf(f0a, s1a, v01a);  v01b = fmaf(f0b, s1b, v01b);
                v10a = fmaf(f1a, s0a, v10a);  v10b = fmaf(f1b, s0b, v10b);
                v11a = fmaf(f1a, s1a, v11a);  v11b = fmaf(f1b, s1b, v11b);
            }
            float4* dst = (right ? g_QR : g_QL) + p * 256;
            dst[m * 8 + qq]       = make_float4(v00a, v00b, v01a, v01b);
            dst[128 + m * 8 + qq] = make_float4(v10a, v10b, v11a, v11b);
        }
    }

    // ---- grid barrier (128 blocks, all co-resident) -------------------------
    __threadfence();
    __syncthreads();
    if (tid == 0) {
        unsigned gen = g_gen;
        if (atomicAdd(&g_count, 1) == (unsigned)(nblocks - 1)) {
            g_count = 0;
            __threadfence();
            g_gen = gen + 1;
        } else {
            while (g_gen == gen) __nanosleep(64);
        }
        __threadfence();
    }
    __syncthreads();

    // ---- chain setup ---------------------------------------------------------
    int pos = __ldg(pos_ptr);
    bool isLeft = (w < 2);
    int wl  = w & 1;
    int sm0 = wl * 8 + ch;                 // local samples
    int sm1 = sm0 + 4;
    int cidx0 = (isLeft ? 0 : 16) + sm0;   // chain slots 0..31
    int cidx1 = (isLeft ? 0 : 16) + sm1;
    int c0 = blockIdx.x * 16 + sm0;
    int c1 = blockIdx.x * 16 + sm1;
    int nsL = pos, nsR = Lm2 - pos;
    int nsites = isLeft ? nsL : nsR;
    int TL = nsL >> 1, TR = nsR >> 1;
    int Tme = nsites >> 1;
    const float* seedA = isLeft ? A_left : A_right;
    int seedX = isLeft ? 0 : (L - 1);

    float sa0 = __ldg(seedA + q),     sa1 = __ldg(seedA + 16 + q);
    float sb0 = __ldg(seedA + q + 8), sb1 = __ldg(seedA + 16 + q + 8);
    float2 xsA = __ldg(in2 + c0 * L + seedX);
    float2 xsB = __ldg(in2 + c1 * L + seedX);
    float vA0 = fmaf(xsA.y, sa1, xsA.x * sa0);
    float vA1 = fmaf(xsA.y, sb1, xsA.x * sb0);
    float vB0 = fmaf(xsB.y, sa1, xsB.x * sa0);
    float vB1 = fmaf(xsB.y, sb1, xsB.x * sb0);
    {   // seed splats -> buffer 0
        float2* dA = sVs + cidx0 * VSTRIDE;
        float2* dB = sVs + cidx1 * VSTRIDE;
        dA[q] = make_float2(vA0, vA0); dA[q + 8] = make_float2(vA1, vA1);
        dB[q] = make_float2(vB0, vB0); dB[q + 8] = make_float2(vB1, vB1);
    }

    unsigned ringAddr = (unsigned)__cvta_generic_to_shared(ring);

    auto stage_pair = [&](int p, int slot) {
#pragma unroll
        for (int kk = 0; kk < 4; ++kk) {
            int chunk  = tid + kk * 128;          // 0..511
            bool isR   = chunk >= 256;
            int within = chunk & 255;
            if (p < (isR ? TR : TL)) {
                const float4* src = (isR ? g_QR : g_QL) + p * 256 + within;
                unsigned dst = ringAddr + slot * SLOT_B + (isR ? QTILE_B : 0)
                             + within * 16;
                cpasync16(dst, src);
            }
        }
        cpcommit();
    };

    auto do_step = [&](int t, int slot) {
        if (t >= Tme) return;
        const char* tile = ring + slot * SLOT_B + (isLeft ? 0 : QTILE_B);
        int vb = t & 1;
        ull vA[16], vB[16];
        {
            const ulonglong2* pa =
                (const ulonglong2*)(sVs + vb * 32 * VSTRIDE + cidx0 * VSTRIDE);
            const ulonglong2* pb =
                (const ulonglong2*)(sVs + vb * 32 * VSTRIDE + cidx1 * VSTRIDE);
#pragma unroll
            for (int j = 0; j < 8; ++j) {
                ulonglong2 ta = pa[j]; vA[2 * j] = ta.x; vA[2 * j + 1] = ta.y;
                ulonglong2 tb = pb[j]; vB[2 * j] = tb.x; vB[2 * j + 1] = tb.y;
            }
        }
        int siteI = isLeft ? (1 + 2 * t) : (L - 3 - 2 * t);
        int siteJ = isLeft ? (2 + 2 * t) : (L - 2 - 2 * t);
        float2 xiA = __ldg(in2 + c0 * L + siteI);
        float2 xjA = __ldg(in2 + c0 * L + siteJ);
        float2 xiB = __ldg(in2 + c1 * L + siteI);
        float2 xjB = __ldg(in2 + c1 * L + siteJ);

        ull aA0=0ull,aA1=0ull,aA2=0ull,aA3=0ull;
        ull aB0=0ull,aB1=0ull,aB2=0ull,aB3=0ull;
#pragma unroll
        for (int m = 0; m < 16; ++m) {
            ulonglong2 M0 = *(const ulonglong2*)(tile + (m * 8 + q) * 16);
            ulonglong2 M1 = *(const ulonglong2*)(tile + 2048 + (m * 8 + q) * 16);
            fma2(aA0, vA[m], M0.x); fma2(aA1, vA[m], M0.y);
            fma2(aA2, vA[m], M1.x); fma2(aA3, vA[m], M1.y);
            fma2(aB0, vB[m], M0.x); fma2(aB1, vB[m], M0.y);
            fma2(aB2, vB[m], M1.x); fma2(aB3, vB[m], M1.y);
        }
        // combine with c_ij = xi[i]*xj[j]
        ull rA = mul2(pack2(xiA.x * xjA.x, xiA.x * xjA.x), aA0);
        fma2(rA, pack2(xiA.x * xjA.y, xiA.x * xjA.y), aA1);
        fma2(rA, pack2(xiA.y * xjA.x, xiA.y * xjA.x), aA2);
        fma2(rA, pack2(xiA.y * xjA.y, xiA.y * xjA.y), aA3);
        unpack2(rA, vA0, vA1);
        ull rB = mul2(pack2(xiB.x * xjB.x, xiB.x * xjB.x), aB0);
        fma2(rB, pack2(xiB.x * xjB.y, xiB.x * xjB.y), aB1);
        fma2(rB, pack2(xiB.y * xjB.x, xiB.y * xjB.x), aB2);
        fma2(rB, pack2(xiB.y * xjB.y, xiB.y * xjB.y), aB3);
        unpack2(rB, vB0, vB1);

        float2* dA = sVs + (1 - vb) * 32 * VSTRIDE + cidx0 * VSTRIDE;
        float2* dB = sVs + (1 - vb) * 32 * VSTRIDE + cidx1 * VSTRIDE;
        dA[q] = make_float2(vA0, vA0); dA[q + 8] = make_float2(vA1, vA1);
        dB[q] = make_float2(vB0, vB0); dB[q + 8] = make_float2(vB1, vB1);
        __syncwarp();
    };

    // ---- main loop: 1 fused step (2 sites) per barrier, 4-slot ring ----------
    int P = (TL > TR ? TL : TR);
    if (P > 0) stage_pair(0, 0); else cpcommit();
    if (P > 1) stage_pair(1, 1); else cpcommit();
    if (P > 2) stage_pair(2, 2); else cpcommit();
    for (int t = 0; t < P; ++t) {
        cpwait<2>();
        __syncthreads();
        if (t + 3 < P) stage_pair(t + 3, (t + 3) & 3); else cpcommit();
        do_step(t, t & 3);
    }
    cpwait<0>();

    // ---- odd tail: one single-site step straight from L2 ---------------------
    if (nsites & 1) {
        int vb = Tme & 1;
        ull vA[16], vB[16];
        {
            const ulonglong2* pa =
                (const ulonglong2*)(sVs + vb * 32 * VSTRIDE + cidx0 * VSTRIDE);
            const ulonglong2* pb =
                (const ulonglong2*)(sVs + vb * 32 * VSTRIDE + cidx1 * VSTRIDE);
#pragma unroll
            for (int j = 0; j < 8; ++j) {
                ulonglong2 ta = pa[j]; vA[2 * j] = ta.x; vA[2 * j + 1] = ta.y;
                ulonglong2 tb = pb[j]; vB[2 * j] = tb.x; vB[2 * j + 1] = tb.y;
            }
        }
        int s = 2 * Tme;                       // remaining site (step index)
        const float4* mat = (isLeft ? g_mat4L : g_mat4R) + s * 128;
        int xin = isLeft ? (1 + s) : (L - 2 - s);
        float2 xA = __ldg(in2 + c0 * L + xin);
        float2 xB = __ldg(in2 + c1 * L + xin);
        ull a0A=0ull,a1A=0ull,a0B=0ull,a1B=0ull;
#pragma unroll
        for (int m = 0; m < 16; ++m) {
            float4 Mf = __ldg(mat + m * 8 + q);
            ull M0 = pack2(Mf.x, Mf.y), M1 = pack2(Mf.z, Mf.w);
            fma2(a0A, vA[m], M0); fma2(a1A, vA[m], M1);
            fma2(a0B, vB[m], M0); fma2(a1B, vB[m], M1);
        }
        ull rA = mul2(pack2(xA.x, xA.x), a0A);
        fma2(rA, pack2(xA.y, xA.y), a1A);
        unpack2(rA, vA0, vA1);
        ull rB = mul2(pack2(xB.x, xB.x), a0B);
        fma2(rB, pack2(xB.y, xB.y), a1B);
        unpack2(rB, vB0, vB1);
    }

    // ---- publish chain results, fused combine --------------------------------
    float* sL = sLR;
    float* sR = sLR + 256;
    {
        float* d = (isLeft ? sL : sR);
        d[sm0 * 16 + q] = vA0; d[sm0 * 16 + q + 8] = vA1;
        d[sm1 * 16 + q] = vB0; d[sm1 * 16 + q + 8] = vB1;
    }
    __syncthreads();

    float* sT = (float*)ring;                       // reuse ring for T
    int tElems = 256 * NBL;
    for (int i = tid; i < tElems; i += 128) sT[i] = __ldg(T + i);
    __syncthreads();

    int total = 16 * NBL;
    for (int i = tid; i < total; i += 128) {
        int b = i / NBL, l = i - b * NBL;
        float acc = 0.f;
#pragma unroll
        for (int m = 0; m < 16; ++m) {
            float t2 = 0.f;
#pragma unroll
            for (int k = 0; k < 16; ++k)
                t2 = fmaf(sT[(m * 16 + k) * NBL + l], sR[b * 16 + k], t2);
            acc = fmaf(sL[b * 16 + m], t2, acc);
        }
        out[(blockIdx.x * 16 + b) * NBL + l] = acc;
    }
}

// ---------------------------------------------------------------------------
extern "C" void kernel_launch(void* const* d_in, const int* in_sizes, int n_in,
                              void* d_out, int out_size) {
    const float* inputs  = (const float*)d_in[0];
    const float* A_left  = (const float*)d_in[1];
    const float* A_mid   = (const float*)d_in[2];
    const float* A_right = (const float*)d_in[3];
    const float* T_out   = (const float*)d_in[4];
    const int*   pos     = (const int*)d_in[5];

    int Lm2 = in_sizes[2] / 512;          // L-2 = 194
    int L   = Lm2 + 2;                    // 196
    int B   = in_sizes[0] / (2 * L);      // 2048
    int NBL = in_sizes[4] / 256;          // 10

    int nblocks = B / 16;                 // 128
    size_t smemB = (size_t)RING_B + SV_B + SLR_B;   // ~43 KB

    cudaFuncSetAttribute(mega_kernel,
                         cudaFuncAttributeMaxDynamicSharedMemorySize,
                         (int)smemB);

    mega_kernel<<<nblocks, 128, smemB>>>(inputs, A_left, A_mid, A_right,
                                         T_out, pos, (float*)d_out,
                                         B, L, NBL, nblocks);
}

// round 12
// speedup vs baseline: 1.4545x; 1.0540x over previous
#include <cuda_runtime.h>

// Shapes (this instance): B=2048, L=196, M=16, NBL=10. Derived from in_sizes.
#define MAXSITES 256
#define MAXPAIRS 128
#define QTILE_B 4096                    // fused pair tile: 256 float4
#define NSLOT   4
#define WRING_B (NSLOT * QTILE_B)       // 16 KB per-warp ring
#define RING_B  (2 * WRING_B)           // 2 warps per block
#define VSTRIDE 18                      // float2 per chain row (144B)
#define SV_B    (2 * 16 * VSTRIDE * 8)  // 4608 B (2 bufs x 16 chains)
#define SLR_B   1024                    // 2 dirs x 8 samples x 16 floats

typedef unsigned long long ull;

// Fused pair tensors (R11-validated):
//  g_QL[p] half0[(m*8+q)] = {P00[m][q],P00[m][q+8],P01[m][q],P01[m][q+8]}
//          half1 = {P10...,P11...};  P_ij = A_i[2p] @ A_j[2p+1]
//  g_QR[p]: right pair p, transposed; P_ij = A_i[Lm2-2-2p] @ A_j[Lm2-1-2p]
__device__ float4 g_QL[MAXPAIRS * 256];
__device__ float4 g_QR[MAXPAIRS * 256];
// Single-site column packs (odd-tail steps):
__device__ float4 g_mat4L[MAXSITES * 128];
__device__ float4 g_mat4R[MAXSITES * 128];
__device__ unsigned g_count = 0;
__device__ volatile unsigned g_gen = 0;

// ---------------------------------------------------------------------------
__device__ __forceinline__ ull pack2(float x, float y) {
    ull r; asm("mov.b64 %0, {%1,%2};" : "=l"(r) : "f"(x), "f"(y)); return r;
}
__device__ __forceinline__ void unpack2(ull v, float& x, float& y) {
    asm("mov.b64 {%0,%1}, %2;" : "=f"(x), "=f"(y) : "l"(v));
}
__device__ __forceinline__ void fma2(ull& d, ull a, ull b) {
    asm("fma.rn.f32x2 %0, %1, %2, %0;" : "+l"(d) : "l"(a), "l"(b));
}
__device__ __forceinline__ ull mul2(ull a, ull b) {
    ull d; asm("mul.rn.f32x2 %0, %1, %2;" : "=l"(d) : "l"(a), "l"(b)); return d;
}
__device__ __forceinline__ void cpasync16(unsigned dst, const void* src) {
    asm volatile("cp.async.cg.shared.global [%0], [%1], 16;\n"
                 :: "r"(dst), "l"(src) : "memory");
}
__device__ __forceinline__ void cpcommit() {
    asm volatile("cp.async.commit_group;\n" ::: "memory");
}
template<int N> __device__ __forceinline__ void cpwait() {
    asm volatile("cp.async.wait_group %0;\n" :: "n"(N) : "memory");
}

// ---------------------------------------------------------------------------
// Megakernel, warp-autonomous main loop.
// Block = 64 thr = 8 samples. Warp 0: LEFT chains, warp 1: RIGHT chains.
// Lane: q = lane&7 owns components {q,q+8}; ch = lane>>3 picks samples
// (ch, ch+4): 2 chains/lane, 8 chains/warp. Per-warp cp.async ring, no
// block barriers in the loop. 256 blocks -> 2 per SM, all co-resident.
// ---------------------------------------------------------------------------
__global__ void __launch_bounds__(64, 2)
mega_kernel(const float* __restrict__ inputs,
            const float* __restrict__ A_left,
            const float* __restrict__ A_mid,
            const float* __restrict__ A_right,
            const float* __restrict__ T,
            const int*   __restrict__ pos_ptr,
            float* __restrict__ out,
            int B, int L, int NBL, int nblocks) {
    extern __shared__ __align__(16) char smem[];
    const int Lm2 = L - 2;
    char*   ring = smem;                                 // RING_B
    float2* sVs  = (float2*)(smem + RING_B);             // SV_B
    float*  sLR  = (float*)(smem + RING_B + SV_B);       // SLR_B

    int tid  = threadIdx.x;
    int w    = tid >> 5;                                 // 0 = left, 1 = right
    int lane = tid & 31;
    int q    = lane & 7;
    int ch   = lane >> 3;                                // 0..3

    const float2* in2 = (const float2*)inputs;           // (B,L) float2

    // ---- prep A: single-site column packs (odd tails) -----------------------
    for (int s = blockIdx.x; s < Lm2; s += nblocks) {
#pragma unroll
        for (int e = tid; e < 128; e += 64) {
            int m = e >> 3, qq = e & 7;
            const float* A0 = A_mid + s * 512;
            const float* A1 = A0 + 256;
            g_mat4L[s * 128 + e] =
                make_float4(A0[m * 16 + qq], A0[m * 16 + qq + 8],
                            A1[m * 16 + qq], A1[m * 16 + qq + 8]);
            g_mat4R[(Lm2 - 1 - s) * 128 + e] =
                make_float4(A0[qq * 16 + m], A0[(qq + 8) * 16 + m],
                            A1[qq * 16 + m], A1[(qq + 8) * 16 + m]);
        }
    }

    // ---- prep B: fused pair products ----------------------------------------
    {
        float* sF = (float*)ring;            // 512 floats
        float* sS = sF + 512;
        int PL = Lm2 >> 1;
        for (int job = blockIdx.x; job < 2 * PL; job += nblocks) {
            bool right = (job >= PL);
            int p = right ? job - PL : job;
            int sFirst  = right ? (Lm2 - 2 - 2 * p) : (2 * p);
            int sSecond = right ? (Lm2 - 1 - 2 * p) : (2 * p + 1);
            __syncthreads();
#pragma unroll
            for (int i = tid; i < 128; i += 64) {
                ((float4*)sF)[i] = __ldg((const float4*)(A_mid + sFirst  * 512) + i);
                ((float4*)sS)[i] = __ldg((const float4*)(A_mid + sSecond * 512) + i);
            }
            __syncthreads();
#pragma unroll
            for (int idx = tid; idx < 128; idx += 64) {
                int m = idx >> 3, qq = idx & 7;
                int rA0 = right ? qq       : m;
                int rA1 = right ? (qq + 8) : m;
                int cB0 = right ? m        : qq;
                int cB1 = right ? m        : (qq + 8);
                float v00a=0,v00b=0,v01a=0,v01b=0,v10a=0,v10b=0,v11a=0,v11b=0;
#pragma unroll
                for (int k = 0; k < 16; ++k) {
                    float f0a = sF[rA0 * 16 + k],       f0b = sF[rA1 * 16 + k];
                    float f1a = sF[256 + rA0 * 16 + k], f1b = sF[256 + rA1 * 16 + k];
                    float s0a = sS[k * 16 + cB0],       s0b = sS[k * 16 + cB1];
                    float s1a = sS[256 + k * 16 + cB0], s1b = sS[256 + k * 16 + cB1];
                    v00a = fmaf(f0a, s0a, v00a);  v00b = fmaf(f0b, s0b, v00b);
                    v01a = fmaf(f0a, s1a, v01a);  v01b = fmaf(f0b, s1b, v01b);
                    v10a = fmaf(f1a, s0a, v10a);  v10b = fmaf(f1b, s0b, v10b);
                    v11a = fmaf(f1a, s1a, v11a);  v11b = fmaf(f1b, s1b, v11b);
                }
                float4* dst = (right ? g_QR : g_QL) + p * 256;
                dst[m * 8 + qq]       = make_float4(v00a, v00b, v01a, v01b);
                dst[128 + m * 8 + qq] = make_float4(v10a, v10b, v11a, v11b);
            }
        }
    }

    // ---- grid barrier (256 blocks, 2/SM, all co-resident) --------------------
    __threadfence();
    __syncthreads();
    if (tid == 0) {
        unsigned gen = g_gen;
        if (atomicAdd(&g_count, 1) == (unsigned)(nblocks - 1)) {
            g_count = 0;
            __threadfence();
            g_gen = gen + 1;
        } else {
            while (g_gen == gen) __nanosleep(64);
        }
        __threadfence();
    }
    __syncthreads();

    // ---- chain setup ----------------------------------------------------------
    int pos = __ldg(pos_ptr);
    bool isLeft = (w == 0);
    int sm0 = ch, sm1 = ch + 4;            // local samples
    int cidx0 = w * 8 + sm0;               // chain slots 0..15
    int cidx1 = w * 8 + sm1;
    int c0 = blockIdx.x * 8 + sm0;
    int c1 = blockIdx.x * 8 + sm1;
    int nsites = isLeft ? pos : (Lm2 - pos);
    int P = nsites >> 1;                   // fused pairs for THIS warp
    const float* seedA = isLeft ? A_left : A_right;
    int seedX = isLeft ? 0 : (L - 1);

    float sa0 = __ldg(seedA + q),     sa1 = __ldg(seedA + 16 + q);
    float sb0 = __ldg(seedA + q + 8), sb1 = __ldg(seedA + 16 + q + 8);
    float2 xsA = __ldg(in2 + c0 * L + seedX);
    float2 xsB = __ldg(in2 + c1 * L + seedX);
    float vA0 = fmaf(xsA.y, sa1, xsA.x * sa0);
    float vA1 = fmaf(xsA.y, sb1, xsA.x * sb0);
    float vB0 = fmaf(xsB.y, sa1, xsB.x * sa0);
    float vB1 = fmaf(xsB.y, sb1, xsB.x * sb0);
    {   // seed splats -> buffer 0
        float2* dA = sVs + cidx0 * VSTRIDE;
        float2* dB = sVs + cidx1 * VSTRIDE;
        dA[q] = make_float2(vA0, vA0); dA[q + 8] = make_float2(vA1, vA1);
        dB[q] = make_float2(vB0, vB0); dB[q + 8] = make_float2(vB1, vB1);
    }

    const float4* QT = isLeft ? g_QL : g_QR;
    unsigned ringW = (unsigned)__cvta_generic_to_shared(ring) + w * WRING_B;

    auto stage = [&](int p, int slot) {
        if (p < P) {
            const float4* src = QT + p * 256;
            unsigned dst = ringW + slot * QTILE_B;
#pragma unroll
            for (int kk = 0; kk < 8; ++kk) {
                int chunk = lane + kk * 32;          // 0..255
                cpasync16(dst + chunk * 16, src + chunk);
            }
        }
        cpcommit();
    };

    auto do_step = [&](int t, int slot,
                       float2 xiA, float2 xjA, float2 xiB, float2 xjB) {
        const char* tile = ring + w * WRING_B + slot * QTILE_B;
        int vb = t & 1;
        ull vA[16], vB[16];
        {
            const ulonglong2* pa =
                (const ulonglong2*)(sVs + vb * 16 * VSTRIDE + cidx0 * VSTRIDE);
            const ulonglong2* pb =
                (const ulonglong2*)(sVs + vb * 16 * VSTRIDE + cidx1 * VSTRIDE);
#pragma unroll
            for (int j = 0; j < 8; ++j) {
                ulonglong2 ta = pa[j]; vA[2 * j] = ta.x; vA[2 * j + 1] = ta.y;
                ulonglong2 tb = pb[j]; vB[2 * j] = tb.x; vB[2 * j + 1] = tb.y;
            }
        }
        ull aA0=0ull,aA1=0ull,aA2=0ull,aA3=0ull;
        ull aB0=0ull,aB1=0ull,aB2=0ull,aB3=0ull;
#pragma unroll
        for (int m = 0; m < 16; ++m) {
            ulonglong2 M0 = *(const ulonglong2*)(tile + (m * 8 + q) * 16);
            ulonglong2 M1 = *(const ulonglong2*)(tile + 2048 + (m * 8 + q) * 16);
            fma2(aA0, vA[m], M0.x); fma2(aA1, vA[m], M0.y);
            fma2(aA2, vA[m], M1.x); fma2(aA3, vA[m], M1.y);
            fma2(aB0, vB[m], M0.x); fma2(aB1, vB[m], M0.y);
            fma2(aB2, vB[m], M1.x); fma2(aB3, vB[m], M1.y);
        }
        ull rA = mul2(pack2(xiA.x * xjA.x, xiA.x * xjA.x), aA0);
        fma2(rA, pack2(xiA.x * xjA.y, xiA.x * xjA.y), aA1);
        fma2(rA, pack2(xiA.y * xjA.x, xiA.y * xjA.x), aA2);
        fma2(rA, pack2(xiA.y * xjA.y, xiA.y * xjA.y), aA3);
        unpack2(rA, vA0, vA1);
        ull rB = mul2(pack2(xiB.x * xjB.x, xiB.x * xjB.x), aB0);
        fma2(rB, pack2(xiB.x * xjB.y, xiB.x * xjB.y), aB1);
        fma2(rB, pack2(xiB.y * xjB.x, xiB.y * xjB.x), aB2);
        fma2(rB, pack2(xiB.y * xjB.y, xiB.y * xjB.y), aB3);
        unpack2(rB, vB0, vB1);

        float2* dA = sVs + (1 - vb) * 16 * VSTRIDE + cidx0 * VSTRIDE;
        float2* dB = sVs + (1 - vb) * 16 * VSTRIDE + cidx1 * VSTRIDE;
        dA[q] = make_float2(vA0, vA0); dA[q + 8] = make_float2(vA1, vA1);
        dB[q] = make_float2(vB0, vB0); dB[q + 8] = make_float2(vB1, vB1);
        __syncwarp();
    };

    // ---- warp-autonomous main loop: no block barriers ------------------------
    stage(0, 0); stage(1, 1); stage(2, 2);

    float2 xiA, xjA, xiB, xjB;
    if (P > 0) {
        int siteI = isLeft ? 1 : (L - 3);
        int siteJ = isLeft ? 2 : (L - 2);
        xiA = __ldg(in2 + c0 * L + siteI); xjA = __ldg(in2 + c0 * L + siteJ);
        xiB = __ldg(in2 + c1 * L + siteI); xjB = __ldg(in2 + c1 * L + siteJ);
    }
    for (int t = 0; t < P; ++t) {
        float2 nxiA, nxjA, nxiB, nxjB;
        if (t + 1 < P) {                   // rolling x prefetch
            int siteI = isLeft ? (3 + 2 * t) : (L - 5 - 2 * t);
            int siteJ = isLeft ? (4 + 2 * t) : (L - 4 - 2 * t);
            nxiA = __ldg(in2 + c0 * L + siteI); nxjA = __ldg(in2 + c0 * L + siteJ);
            nxiB = __ldg(in2 + c1 * L + siteI); nxjB = __ldg(in2 + c1 * L + siteJ);
        }
        cpwait<2>();                       // tile t resident (per-thread groups)
        __syncwarp();                      // publish cp.async data warp-wide
        stage(t + 3, (t + 3) & 3);
        do_step(t, t & 3, xiA, xjA, xiB, xjB);
        xiA = nxiA; xjA = nxjA; xiB = nxiB; xjB = nxjB;
    }
    cpwait<0>();

    // ---- odd tail: one single-site step straight from L2 ----------------------
    if (nsites & 1) {
        int vb = P & 1;
        ull vA[16], vB[16];
        {
            const ulonglong2* pa =
                (const ulonglong2*)(sVs + vb * 16 * VSTRIDE + cidx0 * VSTRIDE);
            const ulonglong2* pb =
                (const ulonglong2*)(sVs + vb * 16 * VSTRIDE + cidx1 * VSTRIDE);
#pragma unroll
            for (int j = 0; j < 8; ++j) {
                ulonglong2 ta = pa[j]; vA[2 * j] = ta.x; vA[2 * j + 1] = ta.y;
                ulonglong2 tb = pb[j]; vB[2 * j] = tb.x; vB[2 * j + 1] = tb.y;
            }
        }
        int s = 2 * P;
        const float4* mat = (isLeft ? g_mat4L : g_mat4R) + s * 128;
        int xin = isLeft ? (1 + s) : (L - 2 - s);
        float2 xA = __ldg(in2 + c0 * L + xin);
        float2 xB = __ldg(in2 + c1 * L + xin);
        ull a0A=0ull,a1A=0ull,a0B=0ull,a1B=0ull;
#pragma unroll
        for (int m = 0; m < 16; ++m) {
            float4 Mf = __ldg(mat + m * 8 + q);
            ull M0 = pack2(Mf.x, Mf.y), M1 = pack2(Mf.z, Mf.w);
            fma2(a0A, vA[m], M0); fma2(a1A, vA[m], M1);
            fma2(a0B, vB[m], M0); fma2(a1B, vB[m], M1);
        }
        ull rA = mul2(pack2(xA.x, xA.x), a0A);
        fma2(rA, pack2(xA.y, xA.y), a1A);
        unpack2(rA, vA0, vA1);
        ull rB = mul2(pack2(xB.x, xB.x), a0B);
        fma2(rB, pack2(xB.y, xB.y), a1B);
        unpack2(rB, vB0, vB1);
    }

    // ---- publish chain results, fused combine ---------------------------------
    float* sL = sLR;
    float* sR = sLR + 128;
    {
        float* d = (isLeft ? sL : sR);
        d[sm0 * 16 + q] = vA0; d[sm0 * 16 + q + 8] = vA1;
        d[sm1 * 16 + q] = vB0; d[sm1 * 16 + q + 8] = vB1;
    }
    __syncthreads();

    float* sT = (float*)ring;                       // reuse ring for T
    int tElems = 256 * NBL;
    for (int i = tid; i < tElems; i += 64) sT[i] = __ldg(T + i);
    __syncthreads();

    int total = 8 * NBL;
    for (int i = tid; i < total; i += 64) {
        int b = i / NBL, l = i - b * NBL;
        float acc = 0.f;
#pragma unroll
        for (int m = 0; m < 16; ++m) {
            float t2 = 0.f;
#pragma unroll
            for (int k = 0; k < 16; ++k)
                t2 = fmaf(sT[(m * 16 + k) * NBL + l], sR[b * 16 + k], t2);
            acc = fmaf(sL[b * 16 + m], t2, acc);
        }
        out[(blockIdx.x * 8 + b) * NBL + l] = acc;
    }
}

// ---------------------------------------------------------------------------
extern "C" void kernel_launch(void* const* d_in, const int* in_sizes, int n_in,
                              void* d_out, int out_size) {
    const float* inputs  = (const float*)d_in[0];
    const float* A_left  = (const float*)d_in[1];
    const float* A_mid   = (const float*)d_in[2];
    const float* A_right = (const float*)d_in[3];
    const float* T_out   = (const float*)d_in[4];
    const int*   pos     = (const int*)d_in[5];

    int Lm2 = in_sizes[2] / 512;          // L-2 = 194
    int L   = Lm2 + 2;                    // 196
    int B   = in_sizes[0] / (2 * L);      // 2048
    int NBL = in_sizes[4] / 256;          // 10

    int nblocks = B / 8;                  // 256 (2 per SM, co-resident)
    size_t smemB = (size_t)RING_B + SV_B + SLR_B;   // ~38 KB

    cudaFuncSetAttribute(mega_kernel,
                         cudaFuncAttributeMaxDynamicSharedMemorySize,
                         (int)smemB);

    mega_kernel<<<nblocks, 64, smemB>>>(inputs, A_left, A_mid, A_right,
                                        T_out, pos, (float*)d_out,
                                        B, L, NBL, nblocks);
}

// round 13
// speedup vs baseline: 1.4651x; 1.0073x over previous
#include <cuda_runtime.h>

// Shapes (this instance): B=2048, L=196, M=16, NBL=10. Derived from in_sizes.
#define MAXSITES 256
#define MAXPAIRS 128
#define QTILE_B 4096                    // fused pair tile: 256 float4
#define NSLOT   6
#define WRING_B (NSLOT * QTILE_B)       // 24 KB per-warp ring
#define RING_B  (2 * WRING_B)           // 2 warps per block
#define VSTRIDE 18                      // float2 per chain row (144B)
#define SV_B    (2 * 16 * VSTRIDE * 8)  // 4608 B (2 bufs x 16 chains)
#define SLR_B   1024                    // 2 dirs x 8 samples x 16 floats

typedef unsigned long long ull;

// Fused pair tensors (R11-validated):
//  g_QL[p] half0[(m*8+q)] = {P00[m][q],P00[m][q+8],P01[m][q],P01[m][q+8]}
//          half1 = {P10...,P11...};  P_ij = A_i[2p] @ A_j[2p+1]
//  g_QR[p]: right pair p, transposed; P_ij = A_i[Lm2-2-2p] @ A_j[Lm2-1-2p]
__device__ float4 g_QL[MAXPAIRS * 256];
__device__ float4 g_QR[MAXPAIRS * 256];
// Single-site column packs (odd-tail steps):
__device__ float4 g_mat4L[MAXSITES * 128];
__device__ float4 g_mat4R[MAXSITES * 128];
__device__ unsigned g_count = 0;
__device__ volatile unsigned g_gen = 0;

// ---------------------------------------------------------------------------
__device__ __forceinline__ ull pack2(float x, float y) {
    ull r; asm("mov.b64 %0, {%1,%2};" : "=l"(r) : "f"(x), "f"(y)); return r;
}
__device__ __forceinline__ void unpack2(ull v, float& x, float& y) {
    asm("mov.b64 {%0,%1}, %2;" : "=f"(x), "=f"(y) : "l"(v));
}
__device__ __forceinline__ void fma2(ull& d, ull a, ull b) {
    asm("fma.rn.f32x2 %0, %1, %2, %0;" : "+l"(d) : "l"(a), "l"(b));
}
__device__ __forceinline__ ull mul2(ull a, ull b) {
    ull d; asm("mul.rn.f32x2 %0, %1, %2;" : "=l"(d) : "l"(a), "l"(b)); return d;
}
// .ca: L1-allocating — same-SM warps reading the same tile hit L1.
__device__ __forceinline__ void cpasyncCA(unsigned dst, const void* src) {
    asm volatile("cp.async.ca.shared.global [%0], [%1], 16;\n"
                 :: "r"(dst), "l"(src) : "memory");
}
__device__ __forceinline__ void cpcommit() {
    asm volatile("cp.async.commit_group;\n" ::: "memory");
}
template<int N> __device__ __forceinline__ void cpwait() {
    asm volatile("cp.async.wait_group %0;\n" :: "n"(N) : "memory");
}

// ---------------------------------------------------------------------------
// Megakernel, warp-autonomous main loop (R12 geometry, staging reworked).
// Block = 64 thr = 8 samples. Warp 0: LEFT chains, warp 1: RIGHT chains.
// Lane: q = lane&7 owns components {q,q+8}; ch = lane>>3 picks samples
// (ch, ch+4): 2 chains/lane, 8 chains/warp. Per-warp 6-slot cp.async.ca ring
// (4 steps of slack), one __syncwarp per step. 256 blocks -> 2 per SM.
// ---------------------------------------------------------------------------
__global__ void __launch_bounds__(64, 2)
mega_kernel(const float* __restrict__ inputs,
            const float* __restrict__ A_left,
            const float* __restrict__ A_mid,
            const float* __restrict__ A_right,
            const float* __restrict__ T,
            const int*   __restrict__ pos_ptr,
            float* __restrict__ out,
            int B, int L, int NBL, int nblocks) {
    extern __shared__ __align__(16) char smem[];
    const int Lm2 = L - 2;
    char*   ring = smem;                                 // RING_B
    float2* sVs  = (float2*)(smem + RING_B);             // SV_B
    float*  sLR  = (float*)(smem + RING_B + SV_B);       // SLR_B

    int tid  = threadIdx.x;
    int w    = tid >> 5;                                 // 0 = left, 1 = right
    int lane = tid & 31;
    int q    = lane & 7;
    int ch   = lane >> 3;                                // 0..3

    const float2* in2 = (const float2*)inputs;           // (B,L) float2

    // ---- prep A: single-site column packs (odd tails) -----------------------
    for (int s = blockIdx.x; s < Lm2; s += nblocks) {
#pragma unroll
        for (int e = tid; e < 128; e += 64) {
            int m = e >> 3, qq = e & 7;
            const float* A0 = A_mid + s * 512;
            const float* A1 = A0 + 256;
            g_mat4L[s * 128 + e] =
                make_float4(A0[m * 16 + qq], A0[m * 16 + qq + 8],
                            A1[m * 16 + qq], A1[m * 16 + qq + 8]);
            g_mat4R[(Lm2 - 1 - s) * 128 + e] =
                make_float4(A0[qq * 16 + m], A0[(qq + 8) * 16 + m],
                            A1[qq * 16 + m], A1[(qq + 8) * 16 + m]);
        }
    }

    // ---- prep B: fused pair products ----------------------------------------
    {
        float* sF = (float*)ring;            // 512 floats
        float* sS = sF + 512;
        int PL = Lm2 >> 1;
        for (int job = blockIdx.x; job < 2 * PL; job += nblocks) {
            bool right = (job >= PL);
            int p = right ? job - PL : job;
            int sFirst  = right ? (Lm2 - 2 - 2 * p) : (2 * p);
            int sSecond = right ? (Lm2 - 1 - 2 * p) : (2 * p + 1);
            __syncthreads();
#pragma unroll
            for (int i = tid; i < 128; i += 64) {
                ((float4*)sF)[i] = __ldg((const float4*)(A_mid + sFirst  * 512) + i);
                ((float4*)sS)[i] = __ldg((const float4*)(A_mid + sSecond * 512) + i);
            }
            __syncthreads();
#pragma unroll
            for (int idx = tid; idx < 128; idx += 64) {
                int m = idx >> 3, qq = idx & 7;
                int rA0 = right ? qq       : m;
                int rA1 = right ? (qq + 8) : m;
                int cB0 = right ? m        : qq;
                int cB1 = right ? m        : (qq + 8);
                float v00a=0,v00b=0,v01a=0,v01b=0,v10a=0,v10b=0,v11a=0,v11b=0;
#pragma unroll
                for (int k = 0; k < 16; ++k) {
                    float f0a = sF[rA0 * 16 + k],       f0b = sF[rA1 * 16 + k];
                    float f1a = sF[256 + rA0 * 16 + k], f1b = sF[256 + rA1 * 16 + k];
                    float s0a = sS[k * 16 + cB0],       s0b = sS[k * 16 + cB1];
                    float s1a = sS[256 + k * 16 + cB0], s1b = sS[256 + k * 16 + cB1];
                    v00a = fmaf(f0a, s0a, v00a);  v00b = fmaf(f0b, s0b, v00b);
                    v01a = fmaf(f0a, s1a, v01a);  v01b = fmaf(f0b, s1b, v01b);
                    v10a = fmaf(f1a, s0a, v10a);  v10b = fmaf(f1b, s0b, v10b);
                    v11a = fmaf(f1a, s1a, v11a);  v11b = fmaf(f1b, s1b, v11b);
                }
                float4* dst = (right ? g_QR : g_QL) + p * 256;
                dst[m * 8 + qq]       = make_float4(v00a, v00b, v01a, v01b);
                dst[128 + m * 8 + qq] = make_float4(v10a, v10b, v11a, v11b);
            }
        }
    }

    // ---- grid barrier (256 blocks, 2/SM, all co-resident) --------------------
    __threadfence();
    __syncthreads();
    if (tid == 0) {
        unsigned gen = g_gen;
        if (atomicAdd(&g_count, 1) == (unsigned)(nblocks - 1)) {
            g_count = 0;
            __threadfence();
            g_gen = gen + 1;
        } else {
            while (g_gen == gen) __nanosleep(64);
        }
        __threadfence();
    }
    __syncthreads();

    // ---- chain setup ----------------------------------------------------------
    int pos = __ldg(pos_ptr);
    bool isLeft = (w == 0);
    int sm0 = ch, sm1 = ch + 4;            // local samples
    int cidx0 = w * 8 + sm0;               // chain slots 0..15
    int cidx1 = w * 8 + sm1;
    int c0 = blockIdx.x * 8 + sm0;
    int c1 = blockIdx.x * 8 + sm1;
    int nsites = isLeft ? pos : (Lm2 - pos);
    int P = nsites >> 1;                   // fused pairs for THIS warp
    const float* seedA = isLeft ? A_left : A_right;
    int seedX = isLeft ? 0 : (L - 1);

    float sa0 = __ldg(seedA + q),     sa1 = __ldg(seedA + 16 + q);
    float sb0 = __ldg(seedA + q + 8), sb1 = __ldg(seedA + 16 + q + 8);
    float2 xsA = __ldg(in2 + c0 * L + seedX);
    float2 xsB = __ldg(in2 + c1 * L + seedX);
    float vA0 = fmaf(xsA.y, sa1, xsA.x * sa0);
    float vA1 = fmaf(xsA.y, sb1, xsA.x * sb0);
    float vB0 = fmaf(xsB.y, sa1, xsB.x * sa0);
    float vB1 = fmaf(xsB.y, sb1, xsB.x * sb0);
    {   // seed splats -> buffer 0
        float2* dA = sVs + cidx0 * VSTRIDE;
        float2* dB = sVs + cidx1 * VSTRIDE;
        dA[q] = make_float2(vA0, vA0); dA[q + 8] = make_float2(vA1, vA1);
        dB[q] = make_float2(vB0, vB0); dB[q + 8] = make_float2(vB1, vB1);
    }

    const float4* QT = isLeft ? g_QL : g_QR;
    unsigned ringW = (unsigned)__cvta_generic_to_shared(ring) + w * WRING_B;

    auto stage = [&](int p, int slot) {
        if (p < P) {
            const float4* src = QT + p * 256;
            unsigned dst = ringW + slot * QTILE_B;
#pragma unroll
            for (int kk = 0; kk < 8; ++kk) {
                int chunk = lane + kk * 32;          // 0..255
                cpasyncCA(dst + chunk * 16, src + chunk);
            }
        }
        cpcommit();
    };

    // coefficient packs for a step (c_ij splatted into f32x2)
    auto make_coef = [&](float2 xi, float2 xj, ull* c) {
        c[0] = pack2(xi.x * xj.x, xi.x * xj.x);
        c[1] = pack2(xi.x * xj.y, xi.x * xj.y);
        c[2] = pack2(xi.y * xj.x, xi.y * xj.x);
        c[3] = pack2(xi.y * xj.y, xi.y * xj.y);
    };

    // do_step: one fused pair; ends with v STS (ordering by NEXT iter's sync).
    auto do_step = [&](int t, int slot, const ull* cA, const ull* cB) {
        const char* tile = ring + w * WRING_B + slot * QTILE_B;
        int vb = t & 1;
        ull vA[16], vB[16];
        {
            const ulonglong2* pa =
                (const ulonglong2*)(sVs + vb * 16 * VSTRIDE + cidx0 * VSTRIDE);
            const ulonglong2* pb =
                (const ulonglong2*)(sVs + vb * 16 * VSTRIDE + cidx1 * VSTRIDE);
#pragma unroll
            for (int j = 0; j < 8; ++j) {
                ulonglong2 ta = pa[j]; vA[2 * j] = ta.x; vA[2 * j + 1] = ta.y;
                ulonglong2 tb = pb[j]; vB[2 * j] = tb.x; vB[2 * j + 1] = tb.y;
            }
        }
        ull aA0=0ull,aA1=0ull,aA2=0ull,aA3=0ull;
        ull aB0=0ull,aB1=0ull,aB2=0ull,aB3=0ull;
#pragma unroll
        for (int m = 0; m < 16; ++m) {
            ulonglong2 M0 = *(const ulonglong2*)(tile + (m * 8 + q) * 16);
            ulonglong2 M1 = *(const ulonglong2*)(tile + 2048 + (m * 8 + q) * 16);
            fma2(aA0, vA[m], M0.x); fma2(aA1, vA[m], M0.y);
            fma2(aA2, vA[m], M1.x); fma2(aA3, vA[m], M1.y);
            fma2(aB0, vB[m], M0.x); fma2(aB1, vB[m], M0.y);
            fma2(aB2, vB[m], M1.x); fma2(aB3, vB[m], M1.y);
        }
        // tree combine (depth 3): (c0*a0 + c1*a1) + (c2*a2 + c3*a3)
        ull rA0 = mul2(cA[0], aA0); fma2(rA0, cA[1], aA1);
        ull rA1 = mul2(cA[2], aA2); fma2(rA1, cA[3], aA3);
        ull rA; asm("add.rn.f32x2 %0, %1, %2;" : "=l"(rA) : "l"(rA0), "l"(rA1));
        unpack2(rA, vA0, vA1);
        ull rB0 = mul2(cB[0], aB0); fma2(rB0, cB[1], aB1);
        ull rB1 = mul2(cB[2], aB2); fma2(rB1, cB[3], aB3);
        ull rB; asm("add.rn.f32x2 %0, %1, %2;" : "=l"(rB) : "l"(rB0), "l"(rB1));
        unpack2(rB, vB0, vB1);

        float2* dA = sVs + (1 - vb) * 16 * VSTRIDE + cidx0 * VSTRIDE;
        float2* dB = sVs + (1 - vb) * 16 * VSTRIDE + cidx1 * VSTRIDE;
        dA[q] = make_float2(vA0, vA0); dA[q + 8] = make_float2(vA1, vA1);
        dB[q] = make_float2(vB0, vB0); dB[q + 8] = make_float2(vB1, vB1);
    };

    // ---- warp-autonomous main loop: 6-slot ring, 4 steps of slack ------------
    stage(0, 0); stage(1, 1); stage(2, 2); stage(3, 3); stage(4, 4);

    ull cA[4], cB[4];
    if (P > 0) {
        int siteI = isLeft ? 1 : (L - 3);
        int siteJ = isLeft ? 2 : (L - 2);
        make_coef(__ldg(in2 + c0 * L + siteI), __ldg(in2 + c0 * L + siteJ), cA);
        make_coef(__ldg(in2 + c1 * L + siteI), __ldg(in2 + c1 * L + siteJ), cB);
    }
    int slotCur = 0, slotPre = 5;
    for (int t = 0; t < P; ++t) {
        float2 nxiA, nxjA, nxiB, nxjB;
        bool more = (t + 1 < P);
        if (more) {                        // rolling x prefetch (issue early)
            int siteI = isLeft ? (3 + 2 * t) : (L - 5 - 2 * t);
            int siteJ = isLeft ? (4 + 2 * t) : (L - 4 - 2 * t);
            nxiA = __ldg(in2 + c0 * L + siteI); nxjA = __ldg(in2 + c0 * L + siteJ);
            nxiB = __ldg(in2 + c1 * L + siteI); nxjB = __ldg(in2 + c1 * L + siteJ);
        }
        cpwait<4>();                       // tile t resident
        __syncwarp();                      // publish cp.async data + prev v STS
        stage(t + 5, slotPre);
        do_step(t, slotCur, cA, cB);
        if (more) {                        // pack coeffs off the critical path
            make_coef(nxiA, nxjA, cA);
            make_coef(nxiB, nxjB, cB);
        }
        slotCur = (slotCur == NSLOT - 1) ? 0 : slotCur + 1;
        slotPre = (slotPre == NSLOT - 1) ? 0 : slotPre + 1;
    }
    cpwait<0>();
    __syncwarp();                          // order last v STS before tail read

    // ---- odd tail: one single-site step straight from L2 ----------------------
    if (nsites & 1) {
        int vb = P & 1;
        ull vA[16], vB[16];
        {
            const ulonglong2* pa =
                (const ulonglong2*)(sVs + vb * 16 * VSTRIDE + cidx0 * VSTRIDE);
            const ulonglong2* pb =
                (const ulonglong2*)(sVs + vb * 16 * VSTRIDE + cidx1 * VSTRIDE);
#pragma unroll
            for (int j = 0; j < 8; ++j) {
                ulonglong2 ta = pa[j]; vA[2 * j] = ta.x; vA[2 * j + 1] = ta.y;
                ulonglong2 tb = pb[j]; vB[2 * j] = tb.x; vB[2 * j + 1] = tb.y;
            }
        }
        int s = 2 * P;
        const float4* mat = (isLeft ? g_mat4L : g_mat4R) + s * 128;
        int xin = isLeft ? (1 + s) : (L - 2 - s);
        float2 xA = __ldg(in2 + c0 * L + xin);
        float2 xB = __ldg(in2 + c1 * L + xin);
        ull a0A=0ull,a1A=0ull,a0B=0ull,a1B=0ull;
#pragma unroll
        for (int m = 0; m < 16; ++m) {
            float4 Mf = __ldg(mat + m * 8 + q);
            ull M0 = pack2(Mf.x, Mf.y), M1 = pack2(Mf.z, Mf.w);
            fma2(a0A, vA[m], M0); fma2(a1A, vA[m], M1);
            fma2(a0B, vB[m], M0); fma2(a1B, vB[m], M1);
        }
        ull rA = mul2(pack2(xA.x, xA.x), a0A);
        fma2(rA, pack2(xA.y, xA.y), a1A);
        unpack2(rA, vA0, vA1);
        ull rB = mul2(pack2(xB.x, xB.x), a0B);
        fma2(rB, pack2(xB.y, xB.y), a1B);
        unpack2(rB, vB0, vB1);
    }

    // ---- publish chain results, fused combine ---------------------------------
    float* sL = sLR;
    float* sR = sLR + 128;
    {
        float* d = (isLeft ? sL : sR);
        d[sm0 * 16 + q] = vA0; d[sm0 * 16 + q + 8] = vA1;
        d[sm1 * 16 + q] = vB0; d[sm1 * 16 + q + 8] = vB1;
    }
    __syncthreads();

    float* sT = (float*)ring;                       // reuse ring for T
    int tElems = 256 * NBL;
    for (int i = tid; i < tElems; i += 64) sT[i] = __ldg(T + i);
    __syncthreads();

    int total = 8 * NBL;
    for (int i = tid; i < total; i += 64) {
        int b = i / NBL, l = i - b * NBL;
        float acc = 0.f;
#pragma unroll
        for (int m = 0; m < 16; ++m) {
            float t2 = 0.f;
#pragma unroll
            for (int k = 0; k < 16; ++k)
                t2 = fmaf(sT[(m * 16 + k) * NBL + l], sR[b * 16 + k], t2);
            acc = fmaf(sL[b * 16 + m], t2, acc);
        }
        out[(blockIdx.x * 8 + b) * NBL + l] = acc;
    }
}

// ---------------------------------------------------------------------------
extern "C" void kernel_launch(void* const* d_in, const int* in_sizes, int n_in,
                              void* d_out, int out_size) {
    const float* inputs  = (const float*)d_in[0];
    const float* A_left  = (const float*)d_in[1];
    const float* A_mid   = (const float*)d_in[2];
    const float* A_right = (const float*)d_in[3];
    const float* T_out   = (const float*)d_in[4];
    const int*   pos     = (const int*)d_in[5];

    int Lm2 = in_sizes[2] / 512;          // L-2 = 194
    int L   = Lm2 + 2;                    // 196
    int B   = in_sizes[0] / (2 * L);      // 2048
    int NBL = in_sizes[4] / 256;          // 10

    int nblocks = B / 8;                  // 256 (2 per SM, co-resident)
    size_t smemB = (size_t)RING_B + SV_B + SLR_B;   // ~55 KB

    cudaFuncSetAttribute(mega_kernel,
                         cudaFuncAttributeMaxDynamicSharedMemorySize,
                         (int)smemB);

    mega_kernel<<<nblocks, 64, smemB>>>(inputs, A_left, A_mid, A_right,
                                        T_out, pos, (float*)d_out,
                                        B, L, NBL, nblocks);
}

// round 14
// speedup vs baseline: 1.5538x; 1.0606x over previous
#include <cuda_runtime.h>

// Shapes (this instance): B=2048, L=196, M=16, NBL=10. Derived from in_sizes.
#define MAXSITES 256
#define MAXPAIRS 128
#define QTILE_B 4096                    // fused pair tile: 256 float4
#define NSLOT   6
#define WRING_B (NSLOT * QTILE_B)       // 24 KB per-warp ring
#define RING_B  (2 * WRING_B)           // 2 warps per block
#define VSTRIDE 18                      // float2 per chain row (144B)
#define SV_B    (2 * 16 * VSTRIDE * 8)  // 4608 B (2 bufs x 16 chains)
#define SLR_B   1024                    // 2 dirs x 8 samples x 16 floats

typedef unsigned long long ull;

// Fused pair tensors (R11-validated):
//  g_QL[p] half0[(m*8+q)] = {P00[m][q],P00[m][q+8],P01[m][q],P01[m][q+8]}
//          half1 = {P10...,P11...};  P_ij = A_i[2p] @ A_j[2p+1]
//  g_QR[p]: right pair p, transposed; P_ij = A_i[Lm2-2-2p] @ A_j[Lm2-1-2p]
__device__ float4 g_QL[MAXPAIRS * 256];
__device__ float4 g_QR[MAXPAIRS * 256];
// Single-site column packs (odd-tail steps):
__device__ float4 g_mat4L[MAXSITES * 128];
__device__ float4 g_mat4R[MAXSITES * 128];

// ---------------------------------------------------------------------------
__device__ __forceinline__ ull pack2(float x, float y) {
    ull r; asm("mov.b64 %0, {%1,%2};" : "=l"(r) : "f"(x), "f"(y)); return r;
}
__device__ __forceinline__ void unpack2(ull v, float& x, float& y) {
    asm("mov.b64 {%0,%1}, %2;" : "=f"(x), "=f"(y) : "l"(v));
}
__device__ __forceinline__ void fma2(ull& d, ull a, ull b) {
    asm("fma.rn.f32x2 %0, %1, %2, %0;" : "+l"(d) : "l"(a), "l"(b));
}
__device__ __forceinline__ ull mul2(ull a, ull b) {
    ull d; asm("mul.rn.f32x2 %0, %1, %2;" : "=l"(d) : "l"(a), "l"(b)); return d;
}
__device__ __forceinline__ void cpasyncCA(unsigned dst, const void* src) {
    asm volatile("cp.async.ca.shared.global [%0], [%1], 16;\n"
                 :: "r"(dst), "l"(src) : "memory");
}
__device__ __forceinline__ void cpcommit() {
    asm volatile("cp.async.commit_group;\n" ::: "memory");
}
template<int N> __device__ __forceinline__ void cpwait() {
    asm volatile("cp.async.wait_group %0;\n" :: "n"(N) : "memory");
}

// ---------------------------------------------------------------------------
// Kernel 1: prep. One site-pair job per block, 256 threads.
// Blocks 0..PL-1: LEFT pair p (+ mat4 packs for sites 2p, 2p+1).
// Blocks PL..2PL-1: RIGHT pair p (transposed product).
// ---------------------------------------------------------------------------
__global__ void __launch_bounds__(256)
prep_kernel(const float* __restrict__ A_mid, int Lm2) {
    __shared__ __align__(16) float sF[512];   // first factor site (A0|A1)
    __shared__ __align__(16) float sS[512];   // second factor site
    int t = threadIdx.x;
    int PL = Lm2 >> 1;
    bool right = (blockIdx.x >= (unsigned)PL);
    int p = right ? blockIdx.x - PL : blockIdx.x;
    int sFirst  = right ? (Lm2 - 2 - 2 * p) : (2 * p);
    int sSecond = right ? (Lm2 - 1 - 2 * p) : (2 * p + 1);

    if (t < 128)
        ((float4*)sF)[t] = __ldg((const float4*)(A_mid + sFirst * 512) + t);
    else
        ((float4*)sS)[t - 128] = __ldg((const float4*)(A_mid + sSecond * 512) + (t - 128));
    __syncthreads();

    // mat4 packs (left blocks cover all even/odd site pairs)
    if (!right) {
        int site = 2 * p + (t >> 7);          // 2p or 2p+1
        const float* S = (t < 128) ? sF : sS;
        int e = t & 127;
        int m = e >> 3, qq = e & 7;
        g_mat4L[site * 128 + e] =
            make_float4(S[m * 16 + qq], S[m * 16 + qq + 8],
                        S[256 + m * 16 + qq], S[256 + m * 16 + qq + 8]);
        g_mat4R[(Lm2 - 1 - site) * 128 + e] =
            make_float4(S[qq * 16 + m], S[(qq + 8) * 16 + m],
                        S[256 + qq * 16 + m], S[256 + (qq + 8) * 16 + m]);
        // odd Lm2 safety: last site packed by block 0 (unused when Lm2 even)
        if (p == 0 && (Lm2 & 1) && t < 128) {
            int s2 = Lm2 - 1;
            const float* A0 = A_mid + s2 * 512;
            const float* A1 = A0 + 256;
            g_mat4L[s2 * 128 + t] =
                make_float4(A0[m * 16 + qq], A0[m * 16 + qq + 8],
                            A1[m * 16 + qq], A1[m * 16 + qq + 8]);
            g_mat4R[(Lm2 - 1 - s2) * 128 + t] =
                make_float4(A0[qq * 16 + m], A0[(qq + 8) * 16 + m],
                            A1[qq * 16 + m], A1[(qq + 8) * 16 + m]);
        }
    }

    // fused pair product: one output float4 per thread
    int h   = t >> 7;                          // which P_h* half
    int idx = t & 127;
    int m = idx >> 3, qq = idx & 7;
    int rA0 = right ? qq       : m;
    int rA1 = right ? (qq + 8) : m;
    int cB0 = right ? m        : qq;
    int cB1 = right ? m        : (qq + 8);
    const float* F = sF + h * 256;             // A_h of first factor
    float o0 = 0.f, o1 = 0.f, o2 = 0.f, o3 = 0.f;
#pragma unroll
    for (int k = 0; k < 16; ++k) {
        float fa = F[rA0 * 16 + k], fb = F[rA1 * 16 + k];
        float s0a = sS[k * 16 + cB0],       s0b = sS[k * 16 + cB1];
        float s1a = sS[256 + k * 16 + cB0], s1b = sS[256 + k * 16 + cB1];
        o0 = fmaf(fa, s0a, o0);  o1 = fmaf(fb, s0b, o1);
        o2 = fmaf(fa, s1a, o2);  o3 = fmaf(fb, s1b, o3);
    }
    float4* dst = (right ? g_QR : g_QL) + p * 256;
    dst[h * 128 + idx] = make_float4(o0, o1, o2, o3);
}

// ---------------------------------------------------------------------------
// Kernel 2: chains + fused combine (R13 loop, prep/barrier removed).
// Block = 64 thr = 8 samples. Warp 0: LEFT, warp 1: RIGHT.
// Lane: q = lane&7 owns components {q,q+8}; ch = lane>>3 picks samples
// (ch, ch+4). Per-warp 6-slot cp.async.ca ring, one __syncwarp per step.
// ---------------------------------------------------------------------------
__global__ void __launch_bounds__(64, 2)
chain_kernel(const float* __restrict__ inputs,
             const float* __restrict__ A_left,
             const float* __restrict__ A_right,
             const float* __restrict__ T,
             const int*   __restrict__ pos_ptr,
             float* __restrict__ out,
             int B, int L, int NBL) {
    extern __shared__ __align__(16) char smem[];
    const int Lm2 = L - 2;
    char*   ring = smem;                                 // RING_B
    float2* sVs  = (float2*)(smem + RING_B);             // SV_B
    float*  sLR  = (float*)(smem + RING_B + SV_B);       // SLR_B

    int tid  = threadIdx.x;
    int w    = tid >> 5;                                 // 0 = left, 1 = right
    int lane = tid & 31;
    int q    = lane & 7;
    int ch   = lane >> 3;                                // 0..3

    const float2* in2 = (const float2*)inputs;           // (B,L) float2

    int pos = __ldg(pos_ptr);
    bool isLeft = (w == 0);
    int sm0 = ch, sm1 = ch + 4;
    int cidx0 = w * 8 + sm0;
    int cidx1 = w * 8 + sm1;
    int c0 = blockIdx.x * 8 + sm0;
    int c1 = blockIdx.x * 8 + sm1;
    int nsites = isLeft ? pos : (Lm2 - pos);
    int P = nsites >> 1;
    const float* seedA = isLeft ? A_left : A_right;
    int seedX = isLeft ? 0 : (L - 1);

    float sa0 = __ldg(seedA + q),     sa1 = __ldg(seedA + 16 + q);
    float sb0 = __ldg(seedA + q + 8), sb1 = __ldg(seedA + 16 + q + 8);
    float2 xsA = __ldg(in2 + c0 * L + seedX);
    float2 xsB = __ldg(in2 + c1 * L + seedX);
    float vA0 = fmaf(xsA.y, sa1, xsA.x * sa0);
    float vA1 = fmaf(xsA.y, sb1, xsA.x * sb0);
    float vB0 = fmaf(xsB.y, sa1, xsB.x * sa0);
    float vB1 = fmaf(xsB.y, sb1, xsB.x * sb0);
    {   // seed splats -> buffer 0
        float2* dA = sVs + cidx0 * VSTRIDE;
        float2* dB = sVs + cidx1 * VSTRIDE;
        dA[q] = make_float2(vA0, vA0); dA[q + 8] = make_float2(vA1, vA1);
        dB[q] = make_float2(vB0, vB0); dB[q + 8] = make_float2(vB1, vB1);
    }

    const float4* QT = isLeft ? g_QL : g_QR;
    unsigned ringW = (unsigned)__cvta_generic_to_shared(ring) + w * WRING_B;

    auto stage = [&](int p, int slot) {
        if (p < P) {
            const float4* src = QT + p * 256;
            unsigned dst = ringW + slot * QTILE_B;
#pragma unroll
            for (int kk = 0; kk < 8; ++kk) {
                int chunk = lane + kk * 32;
                cpasyncCA(dst + chunk * 16, src + chunk);
            }
        }
        cpcommit();
    };

    auto make_coef = [&](float2 xi, float2 xj, ull* c) {
        c[0] = pack2(xi.x * xj.x, xi.x * xj.x);
        c[1] = pack2(xi.x * xj.y, xi.x * xj.y);
        c[2] = pack2(xi.y * xj.x, xi.y * xj.x);
        c[3] = pack2(xi.y * xj.y, xi.y * xj.y);
    };

    auto do_step = [&](int t, int slot, const ull* cA, const ull* cB) {
        const char* tile = ring + w * WRING_B + slot * QTILE_B;
        int vb = t & 1;
        ull vA[16], vB[16];
        {
            const ulonglong2* pa =
                (const ulonglong2*)(sVs + vb * 16 * VSTRIDE + cidx0 * VSTRIDE);
            const ulonglong2* pb =
                (const ulonglong2*)(sVs + vb * 16 * VSTRIDE + cidx1 * VSTRIDE);
#pragma unroll
            for (int j = 0; j < 8; ++j) {
                ulonglong2 ta = pa[j]; vA[2 * j] = ta.x; vA[2 * j + 1] = ta.y;
                ulonglong2 tb = pb[j]; vB[2 * j] = tb.x; vB[2 * j + 1] = tb.y;
            }
        }
        ull aA0=0ull,aA1=0ull,aA2=0ull,aA3=0ull;
        ull aB0=0ull,aB1=0ull,aB2=0ull,aB3=0ull;
#pragma unroll
        for (int m = 0; m < 16; ++m) {
            ulonglong2 M0 = *(const ulonglong2*)(tile + (m * 8 + q) * 16);
            ulonglong2 M1 = *(const ulonglong2*)(tile + 2048 + (m * 8 + q) * 16);
            fma2(aA0, vA[m], M0.x); fma2(aA1, vA[m], M0.y);
            fma2(aA2, vA[m], M1.x); fma2(aA3, vA[m], M1.y);
            fma2(aB0, vB[m], M0.x); fma2(aB1, vB[m], M0.y);
            fma2(aB2, vB[m], M1.x); fma2(aB3, vB[m], M1.y);
        }
        ull rA0 = mul2(cA[0], aA0); fma2(rA0, cA[1], aA1);
        ull rA1 = mul2(cA[2], aA2); fma2(rA1, cA[3], aA3);
        ull rA; asm("add.rn.f32x2 %0, %1, %2;" : "=l"(rA) : "l"(rA0), "l"(rA1));
        unpack2(rA, vA0, vA1);
        ull rB0 = mul2(cB[0], aB0); fma2(rB0, cB[1], aB1);
        ull rB1 = mul2(cB[2], aB2); fma2(rB1, cB[3], aB3);
        ull rB; asm("add.rn.f32x2 %0, %1, %2;" : "=l"(rB) : "l"(rB0), "l"(rB1));
        unpack2(rB, vB0, vB1);

        float2* dA = sVs + (1 - vb) * 16 * VSTRIDE + cidx0 * VSTRIDE;
        float2* dB = sVs + (1 - vb) * 16 * VSTRIDE + cidx1 * VSTRIDE;
        dA[q] = make_float2(vA0, vA0); dA[q + 8] = make_float2(vA1, vA1);
        dB[q] = make_float2(vB0, vB0); dB[q + 8] = make_float2(vB1, vB1);
    };

    // ---- warp-autonomous main loop: 6-slot ring, 4 steps of slack -----------
    stage(0, 0); stage(1, 1); stage(2, 2); stage(3, 3); stage(4, 4);

    ull cA[4], cB[4];
    if (P > 0) {
        int siteI = isLeft ? 1 : (L - 3);
        int siteJ = isLeft ? 2 : (L - 2);
        make_coef(__ldg(in2 + c0 * L + siteI), __ldg(in2 + c0 * L + siteJ), cA);
        make_coef(__ldg(in2 + c1 * L + siteI), __ldg(in2 + c1 * L + siteJ), cB);
    }
    int slotCur = 0, slotPre = 5;
    for (int t = 0; t < P; ++t) {
        float2 nxiA, nxjA, nxiB, nxjB;
        bool more = (t + 1 < P);
        if (more) {
            int siteI = isLeft ? (3 + 2 * t) : (L - 5 - 2 * t);
            int siteJ = isLeft ? (4 + 2 * t) : (L - 4 - 2 * t);
            nxiA = __ldg(in2 + c0 * L + siteI); nxjA = __ldg(in2 + c0 * L + siteJ);
            nxiB = __ldg(in2 + c1 * L + siteI); nxjB = __ldg(in2 + c1 * L + siteJ);
        }
        cpwait<4>();
        __syncwarp();                       // publish cp.async data + prev v STS
        stage(t + 5, slotPre);
        do_step(t, slotCur, cA, cB);
        if (more) {
            make_coef(nxiA, nxjA, cA);
            make_coef(nxiB, nxjB, cB);
        }
        slotCur = (slotCur == NSLOT - 1) ? 0 : slotCur + 1;
        slotPre = (slotPre == NSLOT - 1) ? 0 : slotPre + 1;
    }
    cpwait<0>();
    __syncwarp();

    // ---- odd tail: one single-site step straight from L2 ---------------------
    if (nsites & 1) {
        int vb = P & 1;
        ull vA[16], vB[16];
        {
            const ulonglong2* pa =
                (const ulonglong2*)(sVs + vb * 16 * VSTRIDE + cidx0 * VSTRIDE);
            const ulonglong2* pb =
                (const ulonglong2*)(sVs + vb * 16 * VSTRIDE + cidx1 * VSTRIDE);
#pragma unroll
            for (int j = 0; j < 8; ++j) {
                ulonglong2 ta = pa[j]; vA[2 * j] = ta.x; vA[2 * j + 1] = ta.y;
                ulonglong2 tb = pb[j]; vB[2 * j] = tb.x; vB[2 * j + 1] = tb.y;
            }
        }
        int s = 2 * P;
        const float4* mat = (isLeft ? g_mat4L : g_mat4R) + s * 128;
        int xin = isLeft ? (1 + s) : (L - 2 - s);
        float2 xA = __ldg(in2 + c0 * L + xin);
        float2 xB = __ldg(in2 + c1 * L + xin);
        ull a0A=0ull,a1A=0ull,a0B=0ull,a1B=0ull;
#pragma unroll
        for (int m = 0; m < 16; ++m) {
            float4 Mf = __ldg(mat + m * 8 + q);
            ull M0 = pack2(Mf.x, Mf.y), M1 = pack2(Mf.z, Mf.w);
            fma2(a0A, vA[m], M0); fma2(a1A, vA[m], M1);
            fma2(a0B, vB[m], M0); fma2(a1B, vB[m], M1);
        }
        ull rA = mul2(pack2(xA.x, xA.x), a0A);
        fma2(rA, pack2(xA.y, xA.y), a1A);
        unpack2(rA, vA0, vA1);
        ull rB = mul2(pack2(xB.x, xB.x), a0B);
        fma2(rB, pack2(xB.y, xB.y), a1B);
        unpack2(rB, vB0, vB1);
    }

    // ---- publish chain results, fused combine ---------------------------------
    float* sL = sLR;
    float* sR = sLR + 128;
    {
        float* d = (isLeft ? sL : sR);
        d[sm0 * 16 + q] = vA0; d[sm0 * 16 + q + 8] = vA1;
        d[sm1 * 16 + q] = vB0; d[sm1 * 16 + q + 8] = vB1;
    }
    __syncthreads();

    float* sT = (float*)ring;
    int tElems = 256 * NBL;
    for (int i = tid; i < tElems; i += 64) sT[i] = __ldg(T + i);
    __syncthreads();

    int total = 8 * NBL;
    for (int i = tid; i < total; i += 64) {
        int b = i / NBL, l = i - b * NBL;
        float acc = 0.f;
#pragma unroll
        for (int m = 0; m < 16; ++m) {
            float t2 = 0.f;
#pragma unroll
            for (int k = 0; k < 16; ++k)
                t2 = fmaf(sT[(m * 16 + k) * NBL + l], sR[b * 16 + k], t2);
            acc = fmaf(sL[b * 16 + m], t2, acc);
        }
        out[(blockIdx.x * 8 + b) * NBL + l] = acc;
    }
}

// ---------------------------------------------------------------------------
extern "C" void kernel_launch(void* const* d_in, const int* in_sizes, int n_in,
                              void* d_out, int out_size) {
    const float* inputs  = (const float*)d_in[0];
    const float* A_left  = (const float*)d_in[1];
    const float* A_mid   = (const float*)d_in[2];
    const float* A_right = (const float*)d_in[3];
    const float* T_out   = (const float*)d_in[4];
    const int*   pos     = (const int*)d_in[5];

    int Lm2 = in_sizes[2] / 512;          // L-2 = 194
    int L   = Lm2 + 2;                    // 196
    int B   = in_sizes[0] / (2 * L);      // 2048
    int NBL = in_sizes[4] / 256;          // 10

    int PL = Lm2 >> 1;                    // 97
    prep_kernel<<<2 * PL, 256>>>(A_mid, Lm2);

    int nblocks = B / 8;                  // 256
    size_t smemB = (size_t)RING_B + SV_B + SLR_B;   // ~55 KB

    cudaFuncSetAttribute(chain_kernel,
                         cudaFuncAttributeMaxDynamicSharedMemorySize,
                         (int)smemB);
    chain_kernel<<<nblocks, 64, smemB>>>(inputs, A_left, A_right,
                                         T_out, pos, (float*)d_out,
                                         B, L, NBL);
}